// round 6
// baseline (speedup 1.0000x reference)
#include <cuda_runtime.h>
#include <cstdint>

#define TT 512
#define BB 1024
#define CC 64
#define NEGV (-10000.0f)
#define FULLMASK 0xFFFFFFFFu
#define GRID 148
#define NWARP 8

typedef unsigned long long u64;

// Scratch (no allocations allowed in kernel_launch)
__device__ float g_part[BB];

// ---- packed f32x2 helpers (Blackwell sm_100+); b64 carried as u64 + "l" ----
static __device__ __forceinline__ u64 fma2(u64 a, u64 b, u64 c) {
    u64 r;
    asm("fma.rn.f32x2 %0, %1, %2, %3;" : "=l"(r) : "l"(a), "l"(b), "l"(c));
    return r;
}
static __device__ __forceinline__ u64 add2(u64 a, u64 b) {
    u64 r;
    asm("add.rn.f32x2 %0, %1, %2;" : "=l"(r) : "l"(a), "l"(b));
    return r;
}
static __device__ __forceinline__ u64 pack2(float lo, float hi) {
    u64 r;
    asm("mov.b64 %0, {%1, %2};" : "=l"(r) : "f"(lo), "f"(hi));
    return r;
}
static __device__ __forceinline__ float hadd2(u64 a) {
    float lo, hi;
    asm("mov.b64 {%0, %1}, %2;" : "=f"(lo), "=f"(hi) : "l"(a));
    return lo + hi;
}

// 8 warps/block; warp w of block bl owns chain w*GRID + bl (~7 warps/SM).
// Recursion runs in pivot-normalized probability space:
//   p'_j = acc_j * exp(h_j - h_p) / acc_p,   Mtot += log(acc_p) + h_p
// so no log/exp sits on the per-step critical path.
__global__ void __launch_bounds__(NWARP * 32) crf_chain(
    const float* __restrict__ h,      // (T, B, C)
    const int*   __restrict__ y0,     // (T+1, B)
    const float* __restrict__ mask,   // (T, B)
    const float* __restrict__ trans)  // (C, C)
{
    __shared__ __align__(16) float tr_sh[CC * CC];
    __shared__ __align__(16) float E_sh[CC * CC];          // exp(trans)
    __shared__ __align__(16) u64   p_sh[NWARP][2][32];

    const int tid  = threadIdx.x;
    const int lane = tid & 31;
    const int wid  = tid >> 5;

    // cooperative fill: trans -> tr_sh, exp(trans) -> E_sh
    {
        const float4* g4 = (const float4*)trans;
        float4*       t4 = (float4*)tr_sh;
        float4*       e4 = (float4*)E_sh;
#pragma unroll
        for (int k = 0; k < (CC * CC / 4) / (NWARP * 32); k++) {
            const int    idx = tid + NWARP * 32 * k;
            const float4 v   = g4[idx];
            t4[idx] = v;
            float4 e;
            e.x = __expf(v.x); e.y = __expf(v.y);
            e.z = __expf(v.z); e.w = __expf(v.w);
            e4[idx] = e;
        }
    }
    __syncthreads();

    const int chain = wid * GRID + blockIdx.x;
    if (chain >= BB) return;
    const int b  = chain;
    const int j0 = 2 * lane;
    const int j1 = 2 * lane + 1;

    // E rows -> registers as packed f32x2 pairs: e[k] = (E[j,2k], E[j,2k+1])
    u64 e0[32], e1[32];
    {
        const ulonglong2* ge = (const ulonglong2*)E_sh;
#pragma unroll
        for (int k = 0; k < 16; k++) {
            ulonglong2 q0 = ge[j0 * 16 + k];
            ulonglong2 q1 = ge[j1 * 16 + k];
            e0[2 * k] = q0.x; e0[2 * k + 1] = q0.y;
            e1[2 * k] = q1.x; e1[2 * k + 1] = q1.y;
        }
    }

    // init: Z = NEG except SOS(=1)=0; pivot M=0 -> p = exp(Z)
    float pc0 = (j0 == 1) ? 1.0f : 0.0f;
    float pc1 = (j1 == 1) ? 1.0f : 0.0f;
    p_sh[wid][0][lane] = pack2(pc0, pc1);
    float Mtot = 0.0f;
    __syncwarp();

    // h prefetch: 4 named float2 regs, shifted each step (no dynamic indexing)
    const float2* hp   = (const float2*)h;
    const int     HROW = BB * CC / 2;
    const int     hoff = b * (CC / 2) + lane;
    float2 h1r = hp[0 * HROW + hoff];
    float2 h2r = hp[1 * HROW + hoff];
    float2 h3r = hp[2 * HROW + hoff];
    float2 h4r = hp[3 * HROW + hoff];

    // window 0 labels/mask (+ next-window prefetch regs)
    int      yN    = y0[(1 + lane) * BB + b];
    unsigned mbits = __ballot_sync(FULLMASK, mask[lane * BB + b] != 0.0f);
    int      yN_nx = 0;
    float    mw_nx = 0.0f;

    float S      = 0.0f;
    int   y_prev = 1;   // y0[0] = SOS
    int   buf    = 0;
    int   t      = 0;

#pragma unroll 1
    for (; t < TT; t++) {
        const int s = t & 31;
        if (s == 0) {
            if (t) {
                yN    = yN_nx;
                mbits = __ballot_sync(FULLMASK, mw_nx != 0.0f);
            }
            const int wn = t + 32;
            if (wn < TT) {   // prefetch next window (hidden over 32 steps)
                yN_nx = y0[(wn + 1 + lane) * BB + b];
                mw_nx = mask[(wn + lane) * BB + b];
            }
        }
        if (!((mbits >> s) & 1u)) break;   // mask is monotone

        // consume h(t), shift ring, prefetch h(t+4)
        const float2 hc = h1r;
        h1r = h2r; h2r = h3r; h3r = h4r;
        {
            int tf = t + 4;
            if (tf > TT - 1) tf = TT - 1;
            h4r = hp[(size_t)tf * HROW + hoff];
        }

        // pivot h (state 3 = lane 1 hi) known up-front -> exps run during matvec
        const float hpv = __shfl_sync(FULLMASK, hc.y, 1);
        const float eh0 = __expf(hc.x - hpv);
        const float eh1 = __expf(hc.y - hpv);

        // mat-vec: acc_j = sum_i E[j,i] * p[i]  (packed f32x2, 4 chains/row)
        const ulonglong2* pv = (const ulonglong2*)p_sh[wid][buf];
        u64 a0[4] = {0, 0, 0, 0};
        u64 a1[4] = {0, 0, 0, 0};
#pragma unroll
        for (int k = 0; k < 16; k++) {
            ulonglong2 q = pv[k];
            const int  c = 2 * (k & 1);
            a0[c]     = fma2(e0[2 * k],     q.x, a0[c]);
            a0[c + 1] = fma2(e0[2 * k + 1], q.y, a0[c + 1]);
            a1[c]     = fma2(e1[2 * k],     q.x, a1[c]);
            a1[c + 1] = fma2(e1[2 * k + 1], q.y, a1[c + 1]);
        }
        const float acc0 = hadd2(add2(add2(a0[0], a0[1]), add2(a0[2], a0[3])));
        const float acc1 = hadd2(add2(add2(a1[0], a1[1]), add2(a1[2], a1[3])));

        // pivot-normalize (short serial tail: shfl -> rcp -> mul -> STS)
        const float accp = __shfl_sync(FULLMASK, acc1, 1);
        const float rpp  = __fdividef(1.0f, accp);
        pc0 = acc0 * rpp * eh0;
        pc1 = acc1 * rpp * eh1;
        p_sh[wid][buf ^ 1][lane] = pack2(pc0, pc1);
        buf ^= 1;

        // off-critical-path bookkeeping
        Mtot += __logf(accp) + hpv;

        // score: h[t,b,y_next] via shfl + trans[y_next, y_prev]
        const int   y_next = __shfl_sync(FULLMASK, yN, s);
        const float hlo = __shfl_sync(FULLMASK, hc.x, y_next >> 1);
        const float hhi = __shfl_sync(FULLMASK, hc.y, y_next >> 1);
        const float hv  = (y_next & 1) ? hhi : hlo;
        if (t < TT - 1) S += hv + tr_sh[y_next * CC + y_prev];
        y_prev = y_next;

        __syncwarp();
    }
    const int len = t;

    // final: Zf = Mtot + log( sum_j p_j * exp(trans[EOS, j]) )
    float v = pc0 * E_sh[2 * CC + j0] + pc1 * E_sh[2 * CC + j1];
#pragma unroll
    for (int o = 16; o; o >>= 1) v += __shfl_xor_sync(FULLMASK, v, o);
    const float zf = Mtot + __logf(v);

    // S += trans[PAD, y0[len, b]]
    const int   last = y0[len * BB + b];
    const float Sfin = S + tr_sh[0 * CC + last];

    if (lane == 0) g_part[b] = zf - Sfin;
}

// Deterministic tree reduction of the 1024 per-chain results.
__global__ void crf_reduce(float* __restrict__ out) {
    __shared__ float sh[256];
    const int t = threadIdx.x;
    float s = 0.0f;
#pragma unroll
    for (int k = 0; k < 4; k++) s += g_part[t + 256 * k];
    sh[t] = s;
    __syncthreads();
    for (int o = 128; o; o >>= 1) {
        if (t < o) sh[t] += sh[t + o];
        __syncthreads();
    }
    if (t == 0) out[0] = sh[0] * (1.0f / 1024.0f);
}

extern "C" void kernel_launch(void* const* d_in, const int* in_sizes, int n_in,
                              void* d_out, int out_size) {
    const float* h     = nullptr;
    const int*   y0    = nullptr;
    const float* mask  = nullptr;
    const float* trans = nullptr;
    for (int i = 0; i < n_in; i++) {
        const long n = (long)in_sizes[i];
        if      (n == (long)TT * BB * CC)  h     = (const float*)d_in[i];
        else if (n == (long)(TT + 1) * BB) y0    = (const int*)d_in[i];
        else if (n == (long)TT * BB)       mask  = (const float*)d_in[i];
        else if (n == (long)CC * CC)       trans = (const float*)d_in[i];
    }

    crf_chain<<<GRID, NWARP * 32>>>(h, y0, mask, trans);
    crf_reduce<<<1, 256>>>((float*)d_out);
}

// round 7
// speedup vs baseline: 1.5806x; 1.5806x over previous
#include <cuda_runtime.h>
#include <cstdint>

#define TT 512
#define BB 1024
#define CC 64
#define NEGV (-10000.0f)
#define FULLMASK 0xFFFFFFFFu
#define GRID 148
#define NWARP 8

typedef unsigned long long u64;

__device__ float g_part[BB];

// ---- packed f32x2 helpers (sm_100+): b64 carried as u64 + "l" ----
static __device__ __forceinline__ u64 fma2(u64 a, u64 b, u64 c) {
    u64 r;
    asm("fma.rn.f32x2 %0, %1, %2, %3;" : "=l"(r) : "l"(a), "l"(b), "l"(c));
    return r;
}
static __device__ __forceinline__ u64 add2(u64 a, u64 b) {
    u64 r;
    asm("add.rn.f32x2 %0, %1, %2;" : "=l"(r) : "l"(a), "l"(b));
    return r;
}
static __device__ __forceinline__ u64 pack2(float lo, float hi) {
    u64 r;
    asm("mov.b64 %0, {%1, %2};" : "=l"(r) : "f"(lo), "f"(hi));
    return r;
}
static __device__ __forceinline__ float hadd2(u64 a) {
    float lo, hi;
    asm("mov.b64 {%0, %1}, %2;" : "=f"(lo), "=f"(hi) : "l"(a));
    return lo + hi;
}

// One warp per chain; 8 warps/block; warp w of block bl owns chain w*GRID+bl.
// Ratio-space recursion with DELAYED pivot normalization:
//   stored v_j = acc_j * exp(h_j - h_piv) * (1 / v3_prev)
//   Ccum += log(v3_prev) + h_piv        (exact bookkeeping, off critical path)
// h is prefetched through an 8-deep INDEXED register ring (unroll 8 keeps the
// s&7 indices static -> true dependency distance of 8 steps, hides DRAM lat).
__global__ void __launch_bounds__(NWARP * 32) crf_chain(
    const float* __restrict__ h,      // (T, B, C)
    const int*   __restrict__ y0,     // (T+1, B)
    const float* __restrict__ mask,   // (T, B)
    const float* __restrict__ trans)  // (C, C)
{
    __shared__ __align__(16) float tr_sh[CC * CC];
    __shared__ __align__(16) float E_sh[CC * CC];          // exp(trans)
    __shared__ __align__(16) u64   p_sh[NWARP][2][32];

    const int tid  = threadIdx.x;
    const int lane = tid & 31;
    const int wid  = tid >> 5;

    // cooperative fill: trans -> tr_sh, exp(trans) -> E_sh
    {
        const float4* g4 = (const float4*)trans;
        float4*       t4 = (float4*)tr_sh;
        float4*       e4 = (float4*)E_sh;
#pragma unroll
        for (int k = 0; k < (CC * CC / 4) / (NWARP * 32); k++) {
            const int    idx = tid + NWARP * 32 * k;
            const float4 v   = g4[idx];
            t4[idx] = v;
            float4 e;
            e.x = __expf(v.x); e.y = __expf(v.y);
            e.z = __expf(v.z); e.w = __expf(v.w);
            e4[idx] = e;
        }
    }
    __syncthreads();

    const int chain = wid * GRID + blockIdx.x;
    if (chain >= BB) return;
    const int b  = chain;
    const int j0 = 2 * lane;
    const int j1 = 2 * lane + 1;

    // E rows -> registers as packed f32x2 pairs
    u64 e0[32], e1[32];
    {
        const ulonglong2* ge = (const ulonglong2*)E_sh;
#pragma unroll
        for (int k = 0; k < 16; k++) {
            ulonglong2 q0 = ge[j0 * 16 + k];
            ulonglong2 q1 = ge[j1 * 16 + k];
            e0[2 * k] = q0.x; e0[2 * k + 1] = q0.y;
            e1[2 * k] = q1.x; e1[2 * k + 1] = q1.y;
        }
    }

    // init: v = one-hot at SOS(=1); Ccum = 0; normalizer register seeded to 1
    float pc0 = (j0 == 1) ? 1.0f : 0.0f;
    float pc1 = (j1 == 1) ? 1.0f : 0.0f;
    float nrm_reg = 1.0f;                 // lane 1's copy is v[3]-proxy; 1.0 for step 0
    float Ccum = 0.0f;
    p_sh[wid][0][lane] = pack2(pc0, pc1);
    __syncwarp();

    // 8-deep indexed h ring (float2/lane/step). slot = t & 7 (32 % 8 == 0).
    const float2* hp   = (const float2*)h;
    const int     HROW = BB * CC / 2;
    const int     hoff = b * (CC / 2) + lane;
    float2 hb[8];
#pragma unroll
    for (int k = 0; k < 8; k++) hb[k] = hp[(size_t)k * HROW + hoff];

    // window 0 labels/mask + next-window prefetch
    int      yN    = y0[(1 + lane) * BB + b];
    unsigned mbits = __ballot_sync(FULLMASK, mask[lane * BB + b] != 0.0f);
    int      yN_nx = 0;
    float    mw_nx = 0.0f;

    float S      = 0.0f;
    int   y_prev = 1;   // y0[0] = SOS
    int   len    = TT;
    bool  done   = false;
    int   buf    = 0;

    for (int w = 0; w < TT && !done; w += 32) {
        if (w) {
            yN    = yN_nx;
            mbits = __ballot_sync(FULLMASK, mw_nx != 0.0f);
        }
        const int wn = w + 32;
        if (wn < TT) {    // prefetch next window (latency hidden across 32 steps)
            yN_nx = y0[(wn + 1 + lane) * BB + b];
            mw_nx = mask[(wn + lane) * BB + b];
        }

#pragma unroll 8
        for (int s = 0; s < 32; s++) {
            const int t = w + s;
            if (!((mbits >> s) & 1u)) { len = t; done = true; break; }

            // broadcasts at step start (register shfls; rcp overlaps matvec)
            const float  nrm = __shfl_sync(FULLMASK, nrm_reg, 1);
            const float2 hc  = hb[s & 7];
            const float  hpv = __shfl_sync(FULLMASK, hc.y, 1);
            const float  r   = __fdividef(1.0f, nrm);
            const float  eh0 = __expf(hc.x - hpv);
            const float  eh1 = __expf(hc.y - hpv);
            Ccum += __logf(nrm) + hpv;

            // mat-vec: acc_j = sum_i E[j,i] * v[i]  (packed f32x2, 4 chains/row)
            const ulonglong2* pv = (const ulonglong2*)p_sh[wid][buf];
            u64 a0[4] = {0, 0, 0, 0};
            u64 a1[4] = {0, 0, 0, 0};
#pragma unroll
            for (int k = 0; k < 16; k++) {
                ulonglong2 q = pv[k];
                const int  c = 2 * (k & 1);
                a0[c]     = fma2(e0[2 * k],     q.x, a0[c]);
                a0[c + 1] = fma2(e0[2 * k + 1], q.y, a0[c + 1]);
                a1[c]     = fma2(e1[2 * k],     q.x, a1[c]);
                a1[c + 1] = fma2(e1[2 * k + 1], q.y, a1[c + 1]);
            }
            const float acc0 = hadd2(add2(add2(a0[0], a0[1]), add2(a0[2], a0[3])));
            const float acc1 = hadd2(add2(add2(a1[0], a1[1]), add2(a1[2], a1[3])));

            // short tail: scale, publish, remember next normalizer
            pc0 = acc0 * r * eh0;
            pc1 = acc1 * r * eh1;
            nrm_reg = pc1;                       // lane 1's pc1 == new v[3]
            p_sh[wid][buf ^ 1][lane] = pack2(pc0, pc1);
            buf ^= 1;

            // score: h[t,b,y_next] via shfl + trans[y_next, y_prev]
            const int   y_next = __shfl_sync(FULLMASK, yN, s);
            const float hlo = __shfl_sync(FULLMASK, hc.x, y_next >> 1);
            const float hhi = __shfl_sync(FULLMASK, hc.y, y_next >> 1);
            const float hv  = (y_next & 1) ? hhi : hlo;
            if (t < TT - 1) S += hv + tr_sh[y_next * CC + y_prev];
            y_prev = y_next;

            // refill ring slot (consumed again 8 steps from now)
            {
                int tf = t + 8;
                if (tf > TT - 1) tf = TT - 1;
                hb[s & 7] = hp[(size_t)tf * HROW + hoff];
            }
            __syncwarp();
        }
    }

    // final: Zf = Ccum + log( sum_j v_j * exp(trans[EOS, j]) )
    float v = pc0 * E_sh[2 * CC + j0] + pc1 * E_sh[2 * CC + j1];
#pragma unroll
    for (int o = 16; o; o >>= 1) v += __shfl_xor_sync(FULLMASK, v, o);
    const float zf = Ccum + __logf(v);

    // S += trans[PAD, y0[len, b]]
    const int   last = y0[len * BB + b];
    const float Sfin = S + tr_sh[0 * CC + last];

    if (lane == 0) g_part[b] = zf - Sfin;
}

// Deterministic tree reduction of the 1024 per-chain results.
__global__ void crf_reduce(float* __restrict__ out) {
    __shared__ float sh[256];
    const int t = threadIdx.x;
    float s = 0.0f;
#pragma unroll
    for (int k = 0; k < 4; k++) s += g_part[t + 256 * k];
    sh[t] = s;
    __syncthreads();
    for (int o = 128; o; o >>= 1) {
        if (t < o) sh[t] += sh[t + o];
        __syncthreads();
    }
    if (t == 0) out[0] = sh[0] * (1.0f / 1024.0f);
}

extern "C" void kernel_launch(void* const* d_in, const int* in_sizes, int n_in,
                              void* d_out, int out_size) {
    const float* h     = nullptr;
    const int*   y0    = nullptr;
    const float* mask  = nullptr;
    const float* trans = nullptr;
    for (int i = 0; i < n_in; i++) {
        const long n = (long)in_sizes[i];
        if      (n == (long)TT * BB * CC)  h     = (const float*)d_in[i];
        else if (n == (long)(TT + 1) * BB) y0    = (const int*)d_in[i];
        else if (n == (long)TT * BB)       mask  = (const float*)d_in[i];
        else if (n == (long)CC * CC)       trans = (const float*)d_in[i];
    }

    crf_chain<<<GRID, NWARP * 32>>>(h, y0, mask, trans);
    crf_reduce<<<1, 256>>>((float*)d_out);
}

// round 8
// speedup vs baseline: 1.6968x; 1.0735x over previous
#include <cuda_runtime.h>
#include <cstdint>

#define TT 512
#define BB 1024
#define CC 64
#define FULLMASK 0xFFFFFFFFu
#define GRID 148
#define NWARP 8

typedef unsigned long long u64;

__device__ float g_part[BB];

// ---- packed f32x2 helpers (sm_100+): b64 carried as u64 + "l" ----
static __device__ __forceinline__ u64 fma2(u64 a, u64 b, u64 c) {
    u64 r;
    asm("fma.rn.f32x2 %0, %1, %2, %3;" : "=l"(r) : "l"(a), "l"(b), "l"(c));
    return r;
}
static __device__ __forceinline__ u64 add2(u64 a, u64 b) {
    u64 r;
    asm("add.rn.f32x2 %0, %1, %2;" : "=l"(r) : "l"(a), "l"(b));
    return r;
}
static __device__ __forceinline__ u64 pack2(float lo, float hi) {
    u64 r;
    asm("mov.b64 %0, {%1, %2};" : "=l"(r) : "f"(lo), "f"(hi));
    return r;
}
static __device__ __forceinline__ float hadd2(u64 a) {
    float lo, hi;
    asm("mov.b64 {%0, %1}, %2;" : "=f"(lo), "=f"(hi) : "l"(a));
    return lo + hi;
}

// One warp per chain; 8 warps/block; warp w of block bl owns chain w*GRID+bl.
// v-recursion in scaled probability space (stored v includes exp(h)):
//   v'_j = (sum_i E[j,i] v_i) * exp(h_j) / v3_prev,   Ccum += log(v3_prev)
// Counted loop (len precomputed from monotone mask) -> no per-step branches.
// Score S computed in a separate lane-parallel gather phase.
__global__ void __launch_bounds__(NWARP * 32) crf_chain(
    const float* __restrict__ h,      // (T, B, C)
    const int*   __restrict__ y0,     // (T+1, B)
    const float* __restrict__ mask,   // (T, B)
    const float* __restrict__ trans)  // (C, C)
{
    __shared__ __align__(16) float tr_sh[CC * CC];
    __shared__ __align__(16) float E_sh[CC * CC];          // exp(trans)
    __shared__ __align__(16) u64   p_sh[NWARP][2][32];

    const int tid  = threadIdx.x;
    const int lane = tid & 31;
    const int wid  = tid >> 5;

    // cooperative fill: trans -> tr_sh, exp(trans) -> E_sh
    {
        const float4* g4 = (const float4*)trans;
        float4*       t4 = (float4*)tr_sh;
        float4*       e4 = (float4*)E_sh;
#pragma unroll
        for (int k = 0; k < (CC * CC / 4) / (NWARP * 32); k++) {
            const int    idx = tid + NWARP * 32 * k;
            const float4 v   = g4[idx];
            t4[idx] = v;
            float4 e;
            e.x = __expf(v.x); e.y = __expf(v.y);
            e.z = __expf(v.z); e.w = __expf(v.w);
            e4[idx] = e;
        }
    }
    __syncthreads();

    const int chain = wid * GRID + blockIdx.x;
    if (chain >= BB) return;
    const int b  = chain;
    const int j0 = 2 * lane;
    const int j1 = 2 * lane + 1;

    // chain length: len = sum_t mask[t]  (mask monotone 1...10...0)
    int len;
    {
        float c = 0.0f;
#pragma unroll
        for (int k = 0; k < 16; k++)
            c += mask[(lane + 32 * k) * BB + b];
#pragma unroll
        for (int o = 16; o; o >>= 1) c += __shfl_xor_sync(FULLMASK, c, o);
        len = (int)c;
    }

    // E rows -> registers as packed f32x2 pairs
    u64 e0[32], e1[32];
    {
        const ulonglong2* ge = (const ulonglong2*)E_sh;
#pragma unroll
        for (int k = 0; k < 16; k++) {
            ulonglong2 q0 = ge[j0 * 16 + k];
            ulonglong2 q1 = ge[j1 * 16 + k];
            e0[2 * k] = q0.x; e0[2 * k + 1] = q0.y;
            e1[2 * k] = q1.x; e1[2 * k + 1] = q1.y;
        }
    }

    // init: v = one-hot at SOS(=1); Ccum = 0; normalizer seeded to 1
    float pc0 = (j0 == 1) ? 1.0f : 0.0f;
    float pc1 = (j1 == 1) ? 1.0f : 0.0f;
    float nrm_reg = 1.0f;     // lane 1's copy tracks v[3]
    float Ccum = 0.0f;
    p_sh[wid][0][lane] = pack2(pc0, pc1);
    __syncwarp();

    // 8-deep indexed h ring (float2/lane/step), slot = t & 7
    const float2* hp   = (const float2*)h;
    const int     HROW = BB * CC / 2;
    const int     hoff = b * (CC / 2) + lane;
    float2 hb[8];
#pragma unroll
    for (int k = 0; k < 8; k++) hb[k] = hp[(size_t)k * HROW + hoff];

    int buf = 0;

    // one recursion step; s is the static ring slot ((t & 7) == s by construction)
    auto step = [&](int tcur, int s) __attribute__((always_inline)) {
        const float2 hc  = hb[s];
        const float  nrm = __shfl_sync(FULLMASK, nrm_reg, 1);
        const float  r   = __fdividef(1.0f, nrm);
        const float  eh0 = __expf(hc.x);
        const float  eh1 = __expf(hc.y);
        Ccum += __logf(nrm);

        // mat-vec: acc_j = sum_i E[j,i] * v[i]  (packed f32x2, 4 chains/row)
        const ulonglong2* pv = (const ulonglong2*)p_sh[wid][buf];
        u64 a0[4] = {0, 0, 0, 0};
        u64 a1[4] = {0, 0, 0, 0};
#pragma unroll
        for (int k = 0; k < 16; k++) {
            ulonglong2 q = pv[k];
            const int  c = 2 * (k & 1);
            a0[c]     = fma2(e0[2 * k],     q.x, a0[c]);
            a0[c + 1] = fma2(e0[2 * k + 1], q.y, a0[c + 1]);
            a1[c]     = fma2(e1[2 * k],     q.x, a1[c]);
            a1[c + 1] = fma2(e1[2 * k + 1], q.y, a1[c + 1]);
        }
        const float acc0 = hadd2(add2(add2(a0[0], a0[1]), add2(a0[2], a0[3])));
        const float acc1 = hadd2(add2(add2(a1[0], a1[1]), add2(a1[2], a1[3])));

        pc0 = acc0 * r * eh0;
        pc1 = acc1 * r * eh1;
        nrm_reg = pc1;                        // lane 1's pc1 == new v[3]
        p_sh[wid][buf ^ 1][lane] = pack2(pc0, pc1);
        buf ^= 1;

        // refill ring slot (consumed 8 steps later)
        int tf = tcur + 8;
        if (tf > TT - 1) tf = TT - 1;
        hb[s] = hp[(size_t)tf * HROW + hoff];
        __syncwarp();
    };

    // main counted loop: full chunks of 8, then one break-able tail chunk
    const int len8 = len & ~7;
    int t = 0;
#pragma unroll 1
    for (; t < len8; t += 8) {
#pragma unroll
        for (int s = 0; s < 8; s++) step(t + s, s);
    }
#pragma unroll
    for (int s = 0; s < 8; s++) {
        if (t + s >= len) break;
        step(t + s, s);
    }

    // final: Zf = Ccum + log( sum_j v_j * exp(trans[EOS, j]) )
    float v = pc0 * E_sh[2 * CC + j0] + pc1 * E_sh[2 * CC + j1];
#pragma unroll
    for (int o = 16; o; o >>= 1) v += __shfl_xor_sync(FULLMASK, v, o);
    const float zf = Ccum + __logf(v);

    // score phase: S = sum_{t<min(len,T-1)} h[t,b,y0[t+1]] + trans[y0[t+1],y0[t]]
    float S = 0.0f;
    {
        const int tmax = (len < TT - 1) ? len : (TT - 1);
#pragma unroll
        for (int k = 0; k < 16; k++) {
            const int tt = lane + 32 * k;
            if (tt < tmax) {
                const int ya = y0[tt * BB + b];
                const int yb = y0[(tt + 1) * BB + b];
                const float hv = h[(size_t)tt * (BB * CC) + b * CC + yb];
                S += hv + tr_sh[yb * CC + ya];
            }
        }
#pragma unroll
        for (int o = 16; o; o >>= 1) S += __shfl_xor_sync(FULLMASK, S, o);
    }

    if (lane == 0) {
        const int last = y0[len * BB + b];
        g_part[b] = zf - (S + tr_sh[0 * CC + last]);   // trans[PAD, last]
    }
}

// Deterministic tree reduction of the 1024 per-chain results.
__global__ void crf_reduce(float* __restrict__ out) {
    __shared__ float sh[256];
    const int t = threadIdx.x;
    float s = 0.0f;
#pragma unroll
    for (int k = 0; k < 4; k++) s += g_part[t + 256 * k];
    sh[t] = s;
    __syncthreads();
    for (int o = 128; o; o >>= 1) {
        if (t < o) sh[t] += sh[t + o];
        __syncthreads();
    }
    if (t == 0) out[0] = sh[0] * (1.0f / 1024.0f);
}

extern "C" void kernel_launch(void* const* d_in, const int* in_sizes, int n_in,
                              void* d_out, int out_size) {
    const float* h     = nullptr;
    const int*   y0    = nullptr;
    const float* mask  = nullptr;
    const float* trans = nullptr;
    for (int i = 0; i < n_in; i++) {
        const long n = (long)in_sizes[i];
        if      (n == (long)TT * BB * CC)  h     = (const float*)d_in[i];
        else if (n == (long)(TT + 1) * BB) y0    = (const int*)d_in[i];
        else if (n == (long)TT * BB)       mask  = (const float*)d_in[i];
        else if (n == (long)CC * CC)       trans = (const float*)d_in[i];
    }

    crf_chain<<<GRID, NWARP * 32>>>(h, y0, mask, trans);
    crf_reduce<<<1, 256>>>((float*)d_out);
}

// round 9
// speedup vs baseline: 1.8741x; 1.1045x over previous
#include <cuda_runtime.h>
#include <cstdint>

#define TT 512
#define BB 1024
#define CC 64
#define FULLMASK 0xFFFFFFFFu
#define GRID 148
#define NWARP 8

typedef unsigned long long u64;

__device__ float g_part[BB];
__device__ int   g_lpart[8][BB];   // per-t-slice partial lengths
__device__ int   g_len[BB];
__device__ int   g_order[BB];      // chain ids, descending length

// ---- packed f32x2 helpers (sm_100+): b64 carried as u64 + "l" ----
static __device__ __forceinline__ u64 fma2(u64 a, u64 b, u64 c) {
    u64 r;
    asm("fma.rn.f32x2 %0, %1, %2, %3;" : "=l"(r) : "l"(a), "l"(b), "l"(c));
    return r;
}
static __device__ __forceinline__ u64 add2(u64 a, u64 b) {
    u64 r;
    asm("add.rn.f32x2 %0, %1, %2;" : "=l"(r) : "l"(a), "l"(b));
    return r;
}
static __device__ __forceinline__ u64 pack2(float lo, float hi) {
    u64 r;
    asm("mov.b64 %0, {%1, %2};" : "=l"(r) : "f"(lo), "f"(hi));
    return r;
}
static __device__ __forceinline__ float hadd2(u64 a) {
    float lo, hi;
    asm("mov.b64 {%0, %1}, %2;" : "=f"(lo), "=f"(hi) : "l"(a));
    return lo + hi;
}

// ---- pre-pass 1: per-slice partial lengths (coalesced) ----
__global__ void crf_len(const float* __restrict__ mask) {
    const int b = threadIdx.x;            // 1024 threads
    const int k = blockIdx.x;             // 8 slices of 64 timesteps
    float c = 0.0f;
#pragma unroll 8
    for (int t = k * 64; t < (k + 1) * 64; t++)
        c += mask[t * BB + b];
    g_lpart[k][b] = (int)c;
}

// ---- pre-pass 2: counting sort by length, descending ----
__global__ void crf_sort() {
    __shared__ int hist[TT + 1];
    __shared__ int off[TT + 1];
    const int b = threadIdx.x;            // 1024 threads
    if (b <= TT) hist[b] = 0;
    __syncthreads();
    int len = 0;
#pragma unroll
    for (int k = 0; k < 8; k++) len += g_lpart[k][b];
    g_len[b] = len;
    atomicAdd(&hist[len], 1);
    __syncthreads();
    if (b == 0) {                         // descending exclusive offsets
        int acc = 0;
        for (int l = TT; l >= 0; l--) { off[l] = acc; acc += hist[l]; }
    }
    __syncthreads();
    const int r = atomicAdd(&off[len], 1);
    g_order[r] = b;
}

// One warp per chain. SMSP s hosts wid s and wid s+4; BAND pairs the
// longest band with the shortest so each SMSP gets ~equal total steps.
__global__ void __launch_bounds__(NWARP * 32) crf_chain(
    const float* __restrict__ h,      // (T, B, C)
    const int*   __restrict__ y0,     // (T+1, B)
    const float* __restrict__ mask,   // (T, B)  (unused here)
    const float* __restrict__ trans)  // (C, C)
{
    __shared__ __align__(16) float tr_sh[CC * CC];
    __shared__ __align__(16) float E_sh[CC * CC];          // exp(trans)
    __shared__ __align__(16) u64   p_sh[NWARP][2][32];

    const int tid  = threadIdx.x;
    const int lane = tid & 31;
    const int wid  = tid >> 5;

    // cooperative fill: trans -> tr_sh, exp(trans) -> E_sh
    {
        const float4* g4 = (const float4*)trans;
        float4*       t4 = (float4*)tr_sh;
        float4*       e4 = (float4*)E_sh;
#pragma unroll
        for (int k = 0; k < (CC * CC / 4) / (NWARP * 32); k++) {
            const int    idx = tid + NWARP * 32 * k;
            const float4 v   = g4[idx];
            t4[idx] = v;
            float4 e;
            e.x = __expf(v.x); e.y = __expf(v.y);
            e.z = __expf(v.z); e.w = __expf(v.w);
            e4[idx] = e;
        }
    }
    __syncthreads();

    const int band = (wid < 4) ? wid : 11 - wid;   // {0,1,2,3}->{0..3}, {4..7}->{7,6,5,4}
    const int rank = band * GRID + blockIdx.x;
    if (rank >= BB) return;
    const int b   = g_order[rank];
    const int len = g_len[b];
    const int j0  = 2 * lane;
    const int j1  = 2 * lane + 1;

    // E rows -> registers as packed f32x2 pairs
    u64 e0[32], e1[32];
    {
        const ulonglong2* ge = (const ulonglong2*)E_sh;
#pragma unroll
        for (int k = 0; k < 16; k++) {
            ulonglong2 q0 = ge[j0 * 16 + k];
            ulonglong2 q1 = ge[j1 * 16 + k];
            e0[2 * k] = q0.x; e0[2 * k + 1] = q0.y;
            e1[2 * k] = q1.x; e1[2 * k + 1] = q1.y;
        }
    }

    // init: v one-hot at SOS(=1); Ccum = 0; normalizer seeded to 1
    float pc0 = (j0 == 1) ? 1.0f : 0.0f;
    float pc1 = (j1 == 1) ? 1.0f : 0.0f;
    float nrm_reg = 1.0f;     // lane 1's copy tracks v[3]
    float Ccum = 0.0f;
    p_sh[wid][0][lane] = pack2(pc0, pc1);
    __syncwarp();

    // 8-deep indexed h ring (float2/lane/step), slot = t & 7
    const float2* hp   = (const float2*)h;
    const int     HROW = BB * CC / 2;
    const int     hoff = b * (CC / 2) + lane;
    float2 hb[8];
#pragma unroll
    for (int k = 0; k < 8; k++) hb[k] = hp[(size_t)k * HROW + hoff];

    int buf = 0;

    // one step; s = static ring slot; do_norm at s%4==0 (range audit: inter-norm
    // growth <= e^32, spread <= e^15, well inside fp32)
    auto step = [&](int tcur, int s, bool do_norm) __attribute__((always_inline)) {
        const float2 hc  = hb[s];
        float r = 1.0f;
        if (do_norm) {
            const float nrm = __shfl_sync(FULLMASK, nrm_reg, 1);
            r = __fdividef(1.0f, nrm);
            Ccum += __logf(nrm);
        }
        const float eh0 = __expf(hc.x);
        const float eh1 = __expf(hc.y);

        // mat-vec: acc_j = sum_i E[j,i] * v[i]  (packed f32x2, 4 chains/row)
        const ulonglong2* pv = (const ulonglong2*)p_sh[wid][buf];
        u64 a0[4] = {0, 0, 0, 0};
        u64 a1[4] = {0, 0, 0, 0};
#pragma unroll
        for (int k = 0; k < 16; k++) {
            ulonglong2 q = pv[k];
            const int  c = 2 * (k & 1);
            a0[c]     = fma2(e0[2 * k],     q.x, a0[c]);
            a0[c + 1] = fma2(e0[2 * k + 1], q.y, a0[c + 1]);
            a1[c]     = fma2(e1[2 * k],     q.x, a1[c]);
            a1[c + 1] = fma2(e1[2 * k + 1], q.y, a1[c + 1]);
        }
        const float acc0 = hadd2(add2(add2(a0[0], a0[1]), add2(a0[2], a0[3])));
        const float acc1 = hadd2(add2(add2(a1[0], a1[1]), add2(a1[2], a1[3])));

        if (do_norm) { pc0 = acc0 * r * eh0; pc1 = acc1 * r * eh1; }
        else         { pc0 = acc0 * eh0;     pc1 = acc1 * eh1;     }
        nrm_reg = pc1;                        // lane 1's pc1 == v[3]
        p_sh[wid][buf ^ 1][lane] = pack2(pc0, pc1);
        buf ^= 1;

        // refill ring slot (consumed 8 steps later)
        int tf = tcur + 8;
        if (tf > TT - 1) tf = TT - 1;
        hb[s] = hp[(size_t)tf * HROW + hoff];
        __syncwarp();
    };

    // counted main loop (no per-step branches), then break-able tail chunk
    const int len8 = len & ~7;
    int t = 0;
#pragma unroll 1
    for (; t < len8; t += 8) {
#pragma unroll
        for (int s = 0; s < 8; s++) step(t + s, s, (s & 3) == 0);
    }
#pragma unroll
    for (int s = 0; s < 8; s++) {
        if (t + s >= len) break;
        step(t + s, s, (s & 3) == 0);
    }

    // final: Zf = Ccum + log( sum_j v_j * exp(trans[EOS, j]) )
    float v = pc0 * E_sh[2 * CC + j0] + pc1 * E_sh[2 * CC + j1];
#pragma unroll
    for (int o = 16; o; o >>= 1) v += __shfl_xor_sync(FULLMASK, v, o);
    const float zf = Ccum + __logf(v);

    // score: S = sum_{t<min(len,T-1)} h[t,b,y0[t+1]] + trans[y0[t+1],y0[t]]
    float S = 0.0f;
    {
        const int tmax = (len < TT - 1) ? len : (TT - 1);
#pragma unroll
        for (int k = 0; k < 16; k++) {
            const int tt = lane + 32 * k;
            if (tt < tmax) {
                const int ya = y0[tt * BB + b];
                const int yb = y0[(tt + 1) * BB + b];
                const float hv = h[(size_t)tt * (BB * CC) + b * CC + yb];
                S += hv + tr_sh[yb * CC + ya];
            }
        }
#pragma unroll
        for (int o = 16; o; o >>= 1) S += __shfl_xor_sync(FULLMASK, S, o);
    }

    if (lane == 0) {
        const int last = y0[len * BB + b];
        g_part[b] = zf - (S + tr_sh[0 * CC + last]);   // trans[PAD, last]
    }
}

// Deterministic tree reduction of the 1024 per-chain results.
__global__ void crf_reduce(float* __restrict__ out) {
    __shared__ float sh[256];
    const int t = threadIdx.x;
    float s = 0.0f;
#pragma unroll
    for (int k = 0; k < 4; k++) s += g_part[t + 256 * k];
    sh[t] = s;
    __syncthreads();
    for (int o = 128; o; o >>= 1) {
        if (t < o) sh[t] += sh[t + o];
        __syncthreads();
    }
    if (t == 0) out[0] = sh[0] * (1.0f / 1024.0f);
}

extern "C" void kernel_launch(void* const* d_in, const int* in_sizes, int n_in,
                              void* d_out, int out_size) {
    const float* h     = nullptr;
    const int*   y0    = nullptr;
    const float* mask  = nullptr;
    const float* trans = nullptr;
    for (int i = 0; i < n_in; i++) {
        const long n = (long)in_sizes[i];
        if      (n == (long)TT * BB * CC)  h     = (const float*)d_in[i];
        else if (n == (long)(TT + 1) * BB) y0    = (const int*)d_in[i];
        else if (n == (long)TT * BB)       mask  = (const float*)d_in[i];
        else if (n == (long)CC * CC)       trans = (const float*)d_in[i];
    }

    crf_len<<<8, BB>>>(mask);
    crf_sort<<<1, BB>>>();
    crf_chain<<<GRID, NWARP * 32>>>(h, y0, mask, trans);
    crf_reduce<<<1, 256>>>((float*)d_out);
}